// round 13
// baseline (speedup 1.0000x reference)
#include <cuda_runtime.h>
#include <math.h>

#define N_Q   6
#define N_CL  32
#define N_MOD 32
#define PART  64
#define B_TOTAL   2048
#define N_CLASSES 150
#define K_FINAL   (N_MOD * N_Q)   // 192
#define FEAT_DIM  2048

typedef unsigned long long u64;

// scratch (device globals: allocation-free)
__device__ __align__(16) float g_outs[B_TOTAL * K_FINAL];
__device__ __align__(16) u64   g_useg[2 * N_MOD * 64 * 64];  // [seg][p][col][row] (re,im)
__device__ __align__(16) u64   g_U[N_MOD * 64 * 64];         // [p][row i][col j] (re,im)

// ---- packed f32x2 helpers ----
__device__ __forceinline__ u64 fma2(u64 a, u64 b, u64 c) {
    u64 d; asm("fma.rn.f32x2 %0, %1, %2, %3;" : "=l"(d) : "l"(a), "l"(b), "l"(c)); return d;
}
__device__ __forceinline__ u64 mul2(u64 a, u64 b) {
    u64 d; asm("mul.rn.f32x2 %0, %1, %2;" : "=l"(d) : "l"(a), "l"(b)); return d;
}
__device__ __forceinline__ u64 add2(u64 a, u64 b) {
    u64 d; asm("add.rn.f32x2 %0, %1, %2;" : "=l"(d) : "l"(a), "l"(b)); return d;
}
__device__ __forceinline__ u64 pack2(float lo, float hi) {
    u64 d; asm("mov.b64 %0, {%1, %2};" : "=l"(d) : "f"(lo), "f"(hi)); return d;
}
__device__ __forceinline__ void unpack2(u64 d, float& lo, float& hi) {
    asm("mov.b64 {%0, %1}, %2;" : "=f"(lo), "=f"(hi) : "l"(d));
}

// ===========================================================================
// Kernel 1: segment unitaries. grid (32 mods, 2 segs), block 64: thread = one
// basis column through 16 layers (tan form + deferred cos rescale).
// ===========================================================================
__global__ __launch_bounds__(64) void useg_kernel(const float* __restrict__ qw)
{
    __shared__ float s_tan[16][N_Q];
    __shared__ float s_cs[16][N_Q];
    __shared__ float s_ch[4];

    const int p   = blockIdx.x;
    const int seg = blockIdx.y;
    const int col = threadIdx.x;
    const int tid = threadIdx.x;

    for (int i = tid; i < 16 * N_Q; i += 64) {
        float a = qw[p * (N_CL * N_Q) + seg * 16 * N_Q + i];
        float s, c;
        sincosf(0.5f * a, &s, &c);
        float cc = (fabsf(c) < 1e-12f) ? copysignf(1e-12f, c) : c;
        s_tan[i / N_Q][i % N_Q] = s / cc;
        s_cs[i / N_Q][i % N_Q]  = cc;
    }
    __syncthreads();
    if (tid < 4) {
        float prod = 1.0f;
#pragma unroll
        for (int ll = 0; ll < 4; ll++)
#pragma unroll
            for (int q = 0; q < N_Q; q++)
                prod *= s_cs[tid * 4 + ll][q];
        s_ch[tid] = prod;
    }
    __syncthreads();

    // basis column, packed along amp bit0: reg k = (amp 2k, amp 2k+1)
    u64 srp[32], sip[32];
#pragma unroll
    for (int k = 0; k < 32; k++) {
        srp[k] = pack2(col == 2 * k ? 1.0f : 0.0f, col == 2 * k + 1 ? 1.0f : 0.0f);
        sip[k] = 0ULL;
    }

    for (int ch = 0; ch < 4; ch++) {
#pragma unroll
        for (int l4 = 0; l4 < 4; l4++) {
            const int ll = ch * 4 + l4;
            // RX wires 0..4 (packed)
#pragma unroll
            for (int q = 0; q < 5; q++) {
                const float t = s_tan[ll][q];
                const u64 tv  = pack2(t, t);
                const u64 ntv = pack2(-t, -t);
                const int pb = 4 - q;
                const int m  = 1 << pb;
#pragma unroll
                for (int pr = 0; pr < 16; pr++) {
                    const int k0 = ((pr >> pb) << (pb + 1)) | (pr & (m - 1));
                    const int k1 = k0 | m;
                    u64 a = srp[k0], bb = sip[k0], c2 = srp[k1], d2 = sip[k1];
                    srp[k0] = fma2(tv,  d2, a);
                    sip[k0] = fma2(ntv, c2, bb);
                    srp[k1] = fma2(tv,  bb, c2);
                    sip[k1] = fma2(ntv, a,  d2);
                }
            }
            // RX wire 5 (in-lane)
            {
                const float t = s_tan[ll][5];
#pragma unroll
                for (int k = 0; k < 32; k++) {
                    float r0, r1, u0, u1;
                    unpack2(srp[k], r0, r1);
                    unpack2(sip[k], u0, u1);
                    srp[k] = pack2(fmaf( t, u1, r0), fmaf( t, u0, r1));
                    sip[k] = pack2(fmaf(-t, r1, u0), fmaf(-t, r0, u1));
                }
            }
            // CNOTs q=0..3: register swaps
#pragma unroll
            for (int q = 0; q < 4; q++) {
                const int cbp = 4 - q;
                const int tbp = 3 - q;
                const int tm  = 1 << tbp;
#pragma unroll
                for (int k = 0; k < 32; k++) {
                    if ((((k >> cbp) & 1) == 1) && (((k >> tbp) & 1) == 0)) {
                        const int j = k | tm;
                        u64 tt;
                        tt = srp[k]; srp[k] = srp[j]; srp[j] = tt;
                        tt = sip[k]; sip[k] = sip[j]; sip[j] = tt;
                    }
                }
            }
            // CNOT q=4: swap lanes of odd k
#pragma unroll
            for (int k = 1; k < 32; k += 2) {
                float x, y;
                unpack2(srp[k], x, y); srp[k] = pack2(y, x);
                unpack2(sip[k], x, y); sip[k] = pack2(y, x);
            }
            // CNOT q=5: swap hi lanes of (k, k+16)
#pragma unroll
            for (int k = 0; k < 16; k++) {
                float a0, a1, b0, b1;
                unpack2(srp[k], a0, a1); unpack2(srp[k + 16], b0, b1);
                srp[k] = pack2(a0, b1);  srp[k + 16] = pack2(b0, a1);
                unpack2(sip[k], a0, a1); unpack2(sip[k + 16], b0, b1);
                sip[k] = pack2(a0, b1);  sip[k + 16] = pack2(b0, a1);
            }
        }
        const float lam = s_ch[ch];
        const u64 lamv = pack2(lam, lam);
#pragma unroll
        for (int k = 0; k < 32; k++) {
            srp[k] = mul2(srp[k], lamv);
            sip[k] = mul2(sip[k], lamv);
        }
    }

    u64* dst = g_useg + ((size_t)(seg * N_MOD + p) * 64 + col) * 64;
#pragma unroll
    for (int k = 0; k < 32; k++) {
        float r0, r1, u0, u1;
        unpack2(srp[k], r0, r1);
        unpack2(sip[k], u0, u1);
        dst[2 * k]     = pack2(r0, u0);
        dst[2 * k + 1] = pack2(r1, u1);
    }
}

// ===========================================================================
// Kernel 2: U = S1 * S0 (complex 64x64 per module). grid (32, 4 i-quarters),
// block 128.
// ===========================================================================
__global__ __launch_bounds__(128) void combine_kernel()
{
    __shared__ float sS1r[64 * 17], sS1i[64 * 17];   // [k][i-local pad 17]
    __shared__ float sS0r[64 * 65], sS0i[64 * 65];   // [k][j pad 65]

    const int p   = blockIdx.x;
    const int iq  = blockIdx.y;
    const int tid = threadIdx.x;

    const u64* S0g = g_useg + (size_t)p * 4096;             // seg0: [col j][row k]
    const u64* S1g = g_useg + (size_t)(N_MOD + p) * 4096;   // seg1: [col k][row i]

    for (int g = tid; g < 4096; g += 128) {
        const int j = g >> 6, k = g & 63;
        float re, im;
        unpack2(S0g[g], re, im);
        sS0r[k * 65 + j] = re;
        sS0i[k * 65 + j] = im;
    }
    for (int g = tid; g < 1024; g += 128) {
        const int k = g >> 4, il = g & 15;
        float re, im;
        unpack2(S1g[(size_t)k * 64 + iq * 16 + il], re, im);
        sS1r[k * 17 + il] = re;
        sS1i[k * 17 + il] = im;
    }
    __syncthreads();

    const int ig = tid >> 4;   // 0..7 -> i-local = ig*2 + m
    const int jg = tid & 15;   // j = jg*4 + n
    float cr[2][4], ci[2][4];
#pragma unroll
    for (int m = 0; m < 2; m++)
#pragma unroll
        for (int n = 0; n < 4; n++) { cr[m][n] = 0.0f; ci[m][n] = 0.0f; }

#pragma unroll 4
    for (int k = 0; k < 64; k++) {
        float ar[2], ai[2], br[4], bi[4];
#pragma unroll
        for (int m = 0; m < 2; m++) {
            ar[m] = sS1r[k * 17 + ig * 2 + m];
            ai[m] = sS1i[k * 17 + ig * 2 + m];
        }
#pragma unroll
        for (int n = 0; n < 4; n++) {
            br[n] = sS0r[k * 65 + jg * 4 + n];
            bi[n] = sS0i[k * 65 + jg * 4 + n];
        }
#pragma unroll
        for (int m = 0; m < 2; m++)
#pragma unroll
            for (int n = 0; n < 4; n++) {
                cr[m][n] = fmaf(ar[m], br[n], fmaf(-ai[m], bi[n], cr[m][n]));
                ci[m][n] = fmaf(ar[m], bi[n], fmaf( ai[m], br[n], ci[m][n]));
            }
    }

    u64* Ug = g_U + (size_t)p * 4096;
#pragma unroll
    for (int m = 0; m < 2; m++) {
        const int i = iq * 16 + ig * 2 + m;
#pragma unroll
        for (int n = 0; n < 4; n++) {
            const int j = jg * 4 + n;
            Ug[(size_t)i * 64 + j] = pack2(cr[m][n], ci[m][n]);
        }
    }
}

// ===========================================================================
// Kernel 3: per (module, 64-batch tile): psi build + amps = U*psi (packed
// re/im) + probs + Z-expectations. grid (32 btiles, 32 mods), 128 threads,
// k-split (2 half-j partials), 8x8 register tile, XOR-swizzled U in smem.
// ===========================================================================
__global__ __launch_bounds__(128, 1) void gemm_kernel(
    const float* __restrict__ features,
    const float* __restrict__ Wp,
    const float* __restrict__ bp)
{
    extern __shared__ u64 sm[];
    u64* sU   = sm;            // 4096 u64: [i*64 + (j ^ ((i>>3)&7))] = (Ur,Ui)
    u64* sPsi = sm + 4096;     // [j*64 + b] = (psi,psi)
    __shared__ float sWp[N_Q * PART];
    __shared__ float sBp[N_Q];

    const int p   = blockIdx.y;
    const int b0  = blockIdx.x * 64;
    const int tid = threadIdx.x;

    float4 fr[16];
    if (tid < 64) {
        const float4* fp = (const float4*)(features + (size_t)(b0 + tid) * FEAT_DIM + p * PART);
#pragma unroll
        for (int i = 0; i < 16; i++) fr[i] = fp[i];
    } else {
        const int t = tid - 64;
        for (int i = t; i < N_Q * PART; i += 64) sWp[i] = Wp[i];
        if (t < N_Q) sBp[t] = bp[t];
    }
    __syncthreads();

    if (tid < 64) {
        // ---- psi for batch b0+tid
        float a6[N_Q];
#pragma unroll
        for (int q = 0; q < N_Q; q++) a6[q] = sBp[q];
#pragma unroll
        for (int d4 = 0; d4 < PART / 4; d4++) {
            float4 f = fr[d4];
#pragma unroll
            for (int q = 0; q < N_Q; q++) {
                a6[q] += f.x * sWp[q * PART + d4 * 4 + 0];
                a6[q] += f.y * sWp[q * PART + d4 * 4 + 1];
                a6[q] += f.z * sWp[q * PART + d4 * 4 + 2];
                a6[q] += f.w * sWp[q * PART + d4 * 4 + 3];
            }
        }
        float ca[N_Q], sa[N_Q];
#pragma unroll
        for (int q = 0; q < N_Q; q++) sincosf(0.5f * a6[q], &sa[q], &ca[q]);

        float sr0[64];
        sr0[0] = 1.0f;
#pragma unroll
        for (int q = 0; q < N_Q; q++) {
            const int len = 1 << q;
#pragma unroll
            for (int i = len - 1; i >= 0; i--) {
                float v = sr0[i];
                sr0[2 * i]     = v * ca[q];
                sr0[2 * i + 1] = v * sa[q];
            }
        }
#pragma unroll
        for (int j = 0; j < 64; j++)
            sPsi[j * 64 + tid] = pack2(sr0[j], sr0[j]);
    } else {
        // ---- stage U with XOR swizzle
        const int t = tid - 64;
        const u64* gu = g_U + (size_t)p * 4096;
#pragma unroll
        for (int g = t; g < 4096; g += 64) {
            const int i = g >> 6, j = g & 63;
            sU[i * 64 + (j ^ ((i >> 3) & 7))] = gu[g];
        }
    }
    __syncthreads();

    const int ks = tid >> 6;          // half-j split
    const int ig = (tid >> 3) & 7;    // amp group: i = ig*8 + m
    const int bg = tid & 7;           // batch group: b = bg + 8n

    u64 acc[8][8];
#pragma unroll
    for (int m = 0; m < 8; m++)
#pragma unroll
        for (int n = 0; n < 8; n++) acc[m][n] = 0ULL;

    const u64* su = sU + ig * 512;    // i base = ig*8 rows
    const int jbase = ks * 32;
#pragma unroll 2
    for (int jj = 0; jj < 32; jj++) {
        const int j  = jbase + jj;
        const int jx = j ^ ig;
        u64 uv[8], pv[8];
#pragma unroll
        for (int m = 0; m < 8; m++) uv[m] = su[m * 64 + jx];
#pragma unroll
        for (int n = 0; n < 8; n++) pv[n] = sPsi[j * 64 + bg + 8 * n];
#pragma unroll
        for (int m = 0; m < 8; m++)
#pragma unroll
            for (int n = 0; n < 8; n++)
                acc[m][n] = fma2(uv[m], pv[n], acc[m][n]);
    }
    __syncthreads();

    // ---- k-split reduction via sU region (swizzled to dodge bank conflicts)
    u64* red = sU;
    if (ks) {
        const int t = tid - 64;
#pragma unroll
        for (int m = 0; m < 8; m++)
#pragma unroll
            for (int n = 0; n < 8; n++)
                red[t * 64 + ((m * 8 + n) ^ (t & 15))] = acc[m][n];
    }
    __syncthreads();

    float* sP = (float*)sPsi;   // [b*65 + i] probs
    if (!ks) {
#pragma unroll
        for (int m = 0; m < 8; m++)
#pragma unroll
            for (int n = 0; n < 8; n++) {
                u64 o  = red[tid * 64 + ((m * 8 + n) ^ (tid & 15))];
                u64 s2 = add2(acc[m][n], o);
                float re, im;
                unpack2(s2, re, im);
                sP[(bg + 8 * n) * 65 + ig * 8 + m] = fmaf(re, re, im * im);
            }
    }
    __syncthreads();

    // ---- Z expectations
    for (int task = tid; task < 64 * N_Q; task += 128) {
        const int b  = task & 63;
        const int q  = task >> 6;
        const int sh = 5 - q;
        float s = 0.0f;
#pragma unroll
        for (int i = 0; i < 64; i++) {
            float pv = sP[b * 65 + i];
            s += ((i >> sh) & 1) ? -pv : pv;
        }
        g_outs[(size_t)(b0 + b) * K_FINAL + p * N_Q + q] = s;
    }
}

// ===========================================================================
// Kernel 4: head GEMM out[2048][150] = g_outs @ Wf^T + bf.
// 128 blocks x 256 thr, 16 rows/block, KC=64 chunks, bank-disjoint mapping.
// ===========================================================================
#define HB_M 16
#define HKC  64
#define HPAD 68

__global__ __launch_bounds__(256) void head_kernel(
    const float* __restrict__ Wf,
    const float* __restrict__ bf,
    float* __restrict__ out)
{
    __shared__ float sA[HB_M][HPAD];
    __shared__ float sW[N_CLASSES][HPAD];

    const int tid  = threadIdx.x;
    const int b0   = blockIdx.x * HB_M;
    const int rowg = tid & 7;        // rows rowg, rowg+8
    const int colg = tid >> 3;       // 0..31 (active < 30) -> cols colg*5 .. +4

    float acc[2][5];
#pragma unroll
    for (int m = 0; m < 2; m++)
#pragma unroll
        for (int n = 0; n < 5; n++) acc[m][n] = 0.0f;

    for (int kc = 0; kc < K_FINAL / HKC; kc++) {
        // A: 16 rows x 16 f4 = 256 float4, one per thread (coalesced)
        {
            const int r = tid >> 4, k4 = tid & 15;
            float4 v = *(const float4*)(g_outs + (size_t)(b0 + r) * K_FINAL + kc * HKC + k4 * 4);
            *(float4*)&sA[r][k4 * 4] = v;
        }
        // W: 150 x 16 f4 = 2400 float4
        for (int i = tid; i < N_CLASSES * 16; i += 256) {
            const int r = i >> 4, k4 = i & 15;
            float4 v = __ldg((const float4*)(Wf + (size_t)r * K_FINAL + kc * HKC + k4 * 4));
            *(float4*)&sW[r][k4 * 4] = v;
        }
        __syncthreads();

        if (colg < 30) {
#pragma unroll
            for (int k4 = 0; k4 < HKC / 4; k4++) {
                float4 av[2];
                av[0] = *(const float4*)&sA[rowg][k4 * 4];
                av[1] = *(const float4*)&sA[rowg + 8][k4 * 4];
                float4 wv[5];
#pragma unroll
                for (int n = 0; n < 5; n++)
                    wv[n] = *(const float4*)&sW[colg * 5 + n][k4 * 4];
#pragma unroll
                for (int m = 0; m < 2; m++)
#pragma unroll
                    for (int n = 0; n < 5; n++) {
                        acc[m][n] += av[m].x * wv[n].x;
                        acc[m][n] += av[m].y * wv[n].y;
                        acc[m][n] += av[m].z * wv[n].z;
                        acc[m][n] += av[m].w * wv[n].w;
                    }
            }
        }
        __syncthreads();
    }

    if (colg < 30) {
#pragma unroll
        for (int n = 0; n < 5; n++) {
            const int c = colg * 5 + n;
            const float bias = bf[c];
#pragma unroll
            for (int m = 0; m < 2; m++) {
                const int b = b0 + rowg + 8 * m;
                out[(size_t)b * N_CLASSES + c] = acc[m][n] + bias;
            }
        }
    }
}

extern "C" void kernel_launch(void* const* d_in, const int* in_sizes, int n_in,
                              void* d_out, int out_size)
{
    const float* features = (const float*)d_in[0];
    const float* Wp       = (const float*)d_in[1];
    const float* bp       = (const float*)d_in[2];
    const float* qw       = (const float*)d_in[3];
    const float* Wf       = (const float*)d_in[4];
    const float* bf       = (const float*)d_in[5];
    float* out = (float*)d_out;

    cudaFuncSetAttribute(gemm_kernel, cudaFuncAttributeMaxDynamicSharedMemorySize, 65536);

    useg_kernel<<<dim3(N_MOD, 2), 64>>>(qw);
    combine_kernel<<<dim3(N_MOD, 4), 128>>>();
    gemm_kernel<<<dim3(B_TOTAL / 64, N_MOD), 128, 65536>>>(features, Wp, bp);
    head_kernel<<<B_TOTAL / HB_M, 256>>>(Wf, bf, out);
}

// round 14
// speedup vs baseline: 1.0117x; 1.0117x over previous
#include <cuda_runtime.h>
#include <math.h>

#define N_Q   6
#define N_CL  32
#define N_MOD 32
#define PART  64
#define B_TOTAL   2048
#define N_CLASSES 150
#define K_FINAL   (N_MOD * N_Q)   // 192
#define FEAT_DIM  2048

typedef unsigned long long u64;

// scratch (device globals: allocation-free)
__device__ __align__(16) float g_outs[B_TOTAL * K_FINAL];
__device__ __align__(16) u64   g_useg[2 * N_MOD * 64 * 64];  // [seg][p][col][row] (re,im)
__device__ __align__(16) u64   g_U[N_MOD * 64 * 64];         // [p][row i][col j] (re,im)

// ---- packed f32x2 helpers ----
__device__ __forceinline__ u64 fma2(u64 a, u64 b, u64 c) {
    u64 d; asm("fma.rn.f32x2 %0, %1, %2, %3;" : "=l"(d) : "l"(a), "l"(b), "l"(c)); return d;
}
__device__ __forceinline__ u64 mul2(u64 a, u64 b) {
    u64 d; asm("mul.rn.f32x2 %0, %1, %2;" : "=l"(d) : "l"(a), "l"(b)); return d;
}
__device__ __forceinline__ u64 add2(u64 a, u64 b) {
    u64 d; asm("add.rn.f32x2 %0, %1, %2;" : "=l"(d) : "l"(a), "l"(b)); return d;
}
__device__ __forceinline__ u64 pack2(float lo, float hi) {
    u64 d; asm("mov.b64 %0, {%1, %2};" : "=l"(d) : "f"(lo), "f"(hi)); return d;
}
__device__ __forceinline__ void unpack2(u64 d, float& lo, float& hi) {
    asm("mov.b64 {%0, %1}, %2;" : "=f"(lo), "=f"(hi) : "l"(d));
}

// ===========================================================================
// Kernel 1: segment unitaries. grid (32 mods, 2 segs), block 64: thread = one
// basis column through 16 layers (tan form + deferred cos rescale).
// ===========================================================================
__global__ __launch_bounds__(64) void useg_kernel(const float* __restrict__ qw)
{
    __shared__ float s_tan[16][N_Q];
    __shared__ float s_cs[16][N_Q];
    __shared__ float s_ch[4];

    const int p   = blockIdx.x;
    const int seg = blockIdx.y;
    const int col = threadIdx.x;
    const int tid = threadIdx.x;

    for (int i = tid; i < 16 * N_Q; i += 64) {
        float a = qw[p * (N_CL * N_Q) + seg * 16 * N_Q + i];
        float s, c;
        sincosf(0.5f * a, &s, &c);
        float cc = (fabsf(c) < 1e-12f) ? copysignf(1e-12f, c) : c;
        s_tan[i / N_Q][i % N_Q] = s / cc;
        s_cs[i / N_Q][i % N_Q]  = cc;
    }
    __syncthreads();
    if (tid < 4) {
        float prod = 1.0f;
#pragma unroll
        for (int ll = 0; ll < 4; ll++)
#pragma unroll
            for (int q = 0; q < N_Q; q++)
                prod *= s_cs[tid * 4 + ll][q];
        s_ch[tid] = prod;
    }
    __syncthreads();

    // basis column, packed along amp bit0: reg k = (amp 2k, amp 2k+1)
    u64 srp[32], sip[32];
#pragma unroll
    for (int k = 0; k < 32; k++) {
        srp[k] = pack2(col == 2 * k ? 1.0f : 0.0f, col == 2 * k + 1 ? 1.0f : 0.0f);
        sip[k] = 0ULL;
    }

    for (int ch = 0; ch < 4; ch++) {
#pragma unroll
        for (int l4 = 0; l4 < 4; l4++) {
            const int ll = ch * 4 + l4;
            // RX wires 0..4 (packed)
#pragma unroll
            for (int q = 0; q < 5; q++) {
                const float t = s_tan[ll][q];
                const u64 tv  = pack2(t, t);
                const u64 ntv = pack2(-t, -t);
                const int pb = 4 - q;
                const int m  = 1 << pb;
#pragma unroll
                for (int pr = 0; pr < 16; pr++) {
                    const int k0 = ((pr >> pb) << (pb + 1)) | (pr & (m - 1));
                    const int k1 = k0 | m;
                    u64 a = srp[k0], bb = sip[k0], c2 = srp[k1], d2 = sip[k1];
                    srp[k0] = fma2(tv,  d2, a);
                    sip[k0] = fma2(ntv, c2, bb);
                    srp[k1] = fma2(tv,  bb, c2);
                    sip[k1] = fma2(ntv, a,  d2);
                }
            }
            // RX wire 5 (in-lane)
            {
                const float t = s_tan[ll][5];
#pragma unroll
                for (int k = 0; k < 32; k++) {
                    float r0, r1, u0, u1;
                    unpack2(srp[k], r0, r1);
                    unpack2(sip[k], u0, u1);
                    srp[k] = pack2(fmaf( t, u1, r0), fmaf( t, u0, r1));
                    sip[k] = pack2(fmaf(-t, r1, u0), fmaf(-t, r0, u1));
                }
            }
            // CNOTs q=0..3: register swaps
#pragma unroll
            for (int q = 0; q < 4; q++) {
                const int cbp = 4 - q;
                const int tbp = 3 - q;
                const int tm  = 1 << tbp;
#pragma unroll
                for (int k = 0; k < 32; k++) {
                    if ((((k >> cbp) & 1) == 1) && (((k >> tbp) & 1) == 0)) {
                        const int j = k | tm;
                        u64 tt;
                        tt = srp[k]; srp[k] = srp[j]; srp[j] = tt;
                        tt = sip[k]; sip[k] = sip[j]; sip[j] = tt;
                    }
                }
            }
            // CNOT q=4: swap lanes of odd k
#pragma unroll
            for (int k = 1; k < 32; k += 2) {
                float x, y;
                unpack2(srp[k], x, y); srp[k] = pack2(y, x);
                unpack2(sip[k], x, y); sip[k] = pack2(y, x);
            }
            // CNOT q=5: swap hi lanes of (k, k+16)
#pragma unroll
            for (int k = 0; k < 16; k++) {
                float a0, a1, b0, b1;
                unpack2(srp[k], a0, a1); unpack2(srp[k + 16], b0, b1);
                srp[k] = pack2(a0, b1);  srp[k + 16] = pack2(b0, a1);
                unpack2(sip[k], a0, a1); unpack2(sip[k + 16], b0, b1);
                sip[k] = pack2(a0, b1);  sip[k + 16] = pack2(b0, a1);
            }
        }
        const float lam = s_ch[ch];
        const u64 lamv = pack2(lam, lam);
#pragma unroll
        for (int k = 0; k < 32; k++) {
            srp[k] = mul2(srp[k], lamv);
            sip[k] = mul2(sip[k], lamv);
        }
    }

    u64* dst = g_useg + ((size_t)(seg * N_MOD + p) * 64 + col) * 64;
#pragma unroll
    for (int k = 0; k < 32; k++) {
        float r0, r1, u0, u1;
        unpack2(srp[k], r0, r1);
        unpack2(sip[k], u0, u1);
        dst[2 * k]     = pack2(r0, u0);
        dst[2 * k + 1] = pack2(r1, u1);
    }
}

// ===========================================================================
// Kernel 2: U = S1 * S0 (complex 64x64 per module). grid (32, 4 i-quarters),
// block 128.
// ===========================================================================
__global__ __launch_bounds__(128) void combine_kernel()
{
    __shared__ float sS1r[64 * 17], sS1i[64 * 17];   // [k][i-local pad 17]
    __shared__ float sS0r[64 * 65], sS0i[64 * 65];   // [k][j pad 65]

    const int p   = blockIdx.x;
    const int iq  = blockIdx.y;
    const int tid = threadIdx.x;

    const u64* S0g = g_useg + (size_t)p * 4096;             // seg0: [col j][row k]
    const u64* S1g = g_useg + (size_t)(N_MOD + p) * 4096;   // seg1: [col k][row i]

    for (int g = tid; g < 4096; g += 128) {
        const int j = g >> 6, k = g & 63;
        float re, im;
        unpack2(S0g[g], re, im);
        sS0r[k * 65 + j] = re;
        sS0i[k * 65 + j] = im;
    }
    for (int g = tid; g < 1024; g += 128) {
        const int k = g >> 4, il = g & 15;
        float re, im;
        unpack2(S1g[(size_t)k * 64 + iq * 16 + il], re, im);
        sS1r[k * 17 + il] = re;
        sS1i[k * 17 + il] = im;
    }
    __syncthreads();

    const int ig = tid >> 4;   // 0..7 -> i-local = ig*2 + m
    const int jg = tid & 15;   // j = jg*4 + n
    float cr[2][4], ci[2][4];
#pragma unroll
    for (int m = 0; m < 2; m++)
#pragma unroll
        for (int n = 0; n < 4; n++) { cr[m][n] = 0.0f; ci[m][n] = 0.0f; }

#pragma unroll 4
    for (int k = 0; k < 64; k++) {
        float ar[2], ai[2], br[4], bi[4];
#pragma unroll
        for (int m = 0; m < 2; m++) {
            ar[m] = sS1r[k * 17 + ig * 2 + m];
            ai[m] = sS1i[k * 17 + ig * 2 + m];
        }
#pragma unroll
        for (int n = 0; n < 4; n++) {
            br[n] = sS0r[k * 65 + jg * 4 + n];
            bi[n] = sS0i[k * 65 + jg * 4 + n];
        }
#pragma unroll
        for (int m = 0; m < 2; m++)
#pragma unroll
            for (int n = 0; n < 4; n++) {
                cr[m][n] = fmaf(ar[m], br[n], fmaf(-ai[m], bi[n], cr[m][n]));
                ci[m][n] = fmaf(ar[m], bi[n], fmaf( ai[m], br[n], ci[m][n]));
            }
    }

    u64* Ug = g_U + (size_t)p * 4096;
#pragma unroll
    for (int m = 0; m < 2; m++) {
        const int i = iq * 16 + ig * 2 + m;
#pragma unroll
        for (int n = 0; n < 4; n++) {
            const int j = jg * 4 + n;
            Ug[(size_t)i * 64 + j] = pack2(cr[m][n], ci[m][n]);
        }
    }
}

// ===========================================================================
// Kernel 3: per (module, 64-batch tile): psi build + amps = U*psi (packed
// re/im) + probs + Z-expectations. grid (32 btiles, 32 mods), 128 threads,
// k-split (2 half-j partials), 8x8 register tile, XOR-swizzled U in smem.
// ===========================================================================
__global__ __launch_bounds__(128, 1) void gemm_kernel(
    const float* __restrict__ features,
    const float* __restrict__ Wp,
    const float* __restrict__ bp)
{
    extern __shared__ u64 sm[];
    u64* sU   = sm;            // 4096 u64: [i*64 + (j ^ ((i>>3)&7))] = (Ur,Ui)
    u64* sPsi = sm + 4096;     // [j*64 + b] = (psi,psi)
    __shared__ float sWp[N_Q * PART];
    __shared__ float sBp[N_Q];

    const int p   = blockIdx.y;
    const int b0  = blockIdx.x * 64;
    const int tid = threadIdx.x;

    float4 fr[16];
    if (tid < 64) {
        const float4* fp = (const float4*)(features + (size_t)(b0 + tid) * FEAT_DIM + p * PART);
#pragma unroll
        for (int i = 0; i < 16; i++) fr[i] = fp[i];
    } else {
        const int t = tid - 64;
        for (int i = t; i < N_Q * PART; i += 64) sWp[i] = Wp[i];
        if (t < N_Q) sBp[t] = bp[t];
    }
    __syncthreads();

    if (tid < 64) {
        // ---- psi for batch b0+tid
        float a6[N_Q];
#pragma unroll
        for (int q = 0; q < N_Q; q++) a6[q] = sBp[q];
#pragma unroll
        for (int d4 = 0; d4 < PART / 4; d4++) {
            float4 f = fr[d4];
#pragma unroll
            for (int q = 0; q < N_Q; q++) {
                a6[q] += f.x * sWp[q * PART + d4 * 4 + 0];
                a6[q] += f.y * sWp[q * PART + d4 * 4 + 1];
                a6[q] += f.z * sWp[q * PART + d4 * 4 + 2];
                a6[q] += f.w * sWp[q * PART + d4 * 4 + 3];
            }
        }
        float ca[N_Q], sa[N_Q];
#pragma unroll
        for (int q = 0; q < N_Q; q++) sincosf(0.5f * a6[q], &sa[q], &ca[q]);

        float sr0[64];
        sr0[0] = 1.0f;
#pragma unroll
        for (int q = 0; q < N_Q; q++) {
            const int len = 1 << q;
#pragma unroll
            for (int i = len - 1; i >= 0; i--) {
                float v = sr0[i];
                sr0[2 * i]     = v * ca[q];
                sr0[2 * i + 1] = v * sa[q];
            }
        }
#pragma unroll
        for (int j = 0; j < 64; j++)
            sPsi[j * 64 + tid] = pack2(sr0[j], sr0[j]);
    } else {
        // ---- stage U with XOR swizzle
        const int t = tid - 64;
        const u64* gu = g_U + (size_t)p * 4096;
#pragma unroll
        for (int g = t; g < 4096; g += 64) {
            const int i = g >> 6, j = g & 63;
            sU[i * 64 + (j ^ ((i >> 3) & 7))] = gu[g];
        }
    }
    __syncthreads();

    const int ks = tid >> 6;          // half-j split
    const int ig = (tid >> 3) & 7;    // amp group: i = ig*8 + m
    const int bg = tid & 7;           // batch group: b = bg + 8n

    u64 acc[8][8];
#pragma unroll
    for (int m = 0; m < 8; m++)
#pragma unroll
        for (int n = 0; n < 8; n++) acc[m][n] = 0ULL;

    const u64* su = sU + ig * 512;    // i base = ig*8 rows
    const int jbase = ks * 32;
#pragma unroll 2
    for (int jj = 0; jj < 32; jj++) {
        const int j  = jbase + jj;
        const int jx = j ^ ig;
        u64 uv[8], pv[8];
#pragma unroll
        for (int m = 0; m < 8; m++) uv[m] = su[m * 64 + jx];
#pragma unroll
        for (int n = 0; n < 8; n++) pv[n] = sPsi[j * 64 + bg + 8 * n];
#pragma unroll
        for (int m = 0; m < 8; m++)
#pragma unroll
            for (int n = 0; n < 8; n++)
                acc[m][n] = fma2(uv[m], pv[n], acc[m][n]);
    }
    __syncthreads();

    // ---- k-split reduction via sU region (swizzled to dodge bank conflicts)
    u64* red = sU;
    if (ks) {
        const int t = tid - 64;
#pragma unroll
        for (int m = 0; m < 8; m++)
#pragma unroll
            for (int n = 0; n < 8; n++)
                red[t * 64 + ((m * 8 + n) ^ (t & 15))] = acc[m][n];
    }
    __syncthreads();

    float* sP = (float*)sPsi;   // [b*65 + i] probs
    if (!ks) {
#pragma unroll
        for (int m = 0; m < 8; m++)
#pragma unroll
            for (int n = 0; n < 8; n++) {
                u64 o  = red[tid * 64 + ((m * 8 + n) ^ (tid & 15))];
                u64 s2 = add2(acc[m][n], o);
                float re, im;
                unpack2(s2, re, im);
                sP[(bg + 8 * n) * 65 + ig * 8 + m] = fmaf(re, re, im * im);
            }
    }
    __syncthreads();

    // ---- Z expectations
    for (int task = tid; task < 64 * N_Q; task += 128) {
        const int b  = task & 63;
        const int q  = task >> 6;
        const int sh = 5 - q;
        float s = 0.0f;
#pragma unroll
        for (int i = 0; i < 64; i++) {
            float pv = sP[b * 65 + i];
            s += ((i >> sh) & 1) ? -pv : pv;
        }
        g_outs[(size_t)(b0 + b) * K_FINAL + p * N_Q + q] = s;
    }
}

// ===========================================================================
// Kernel 4: head GEMM out[2048][150] = g_outs @ Wf^T + bf.
// 128 blocks x 256 thr, 16 rows/block, KC=64 chunks, bank-disjoint mapping.
// ===========================================================================
#define HB_M 16
#define HKC  64
#define HPAD 68

__global__ __launch_bounds__(256) void head_kernel(
    const float* __restrict__ Wf,
    const float* __restrict__ bf,
    float* __restrict__ out)
{
    __shared__ float sA[HB_M][HPAD];
    __shared__ float sW[N_CLASSES][HPAD];

    const int tid  = threadIdx.x;
    const int b0   = blockIdx.x * HB_M;
    const int rowg = tid & 7;        // rows rowg, rowg+8
    const int colg = tid >> 3;       // 0..31 (active < 30) -> cols colg*5 .. +4

    float acc[2][5];
#pragma unroll
    for (int m = 0; m < 2; m++)
#pragma unroll
        for (int n = 0; n < 5; n++) acc[m][n] = 0.0f;

    for (int kc = 0; kc < K_FINAL / HKC; kc++) {
        // A: 16 rows x 16 f4 = 256 float4, one per thread (coalesced)
        {
            const int r = tid >> 4, k4 = tid & 15;
            float4 v = *(const float4*)(g_outs + (size_t)(b0 + r) * K_FINAL + kc * HKC + k4 * 4);
            *(float4*)&sA[r][k4 * 4] = v;
        }
        // W: 150 x 16 f4 = 2400 float4
        for (int i = tid; i < N_CLASSES * 16; i += 256) {
            const int r = i >> 4, k4 = i & 15;
            float4 v = __ldg((const float4*)(Wf + (size_t)r * K_FINAL + kc * HKC + k4 * 4));
            *(float4*)&sW[r][k4 * 4] = v;
        }
        __syncthreads();

        if (colg < 30) {
#pragma unroll
            for (int k4 = 0; k4 < HKC / 4; k4++) {
                float4 av[2];
                av[0] = *(const float4*)&sA[rowg][k4 * 4];
                av[1] = *(const float4*)&sA[rowg + 8][k4 * 4];
                float4 wv[5];
#pragma unroll
                for (int n = 0; n < 5; n++)
                    wv[n] = *(const float4*)&sW[colg * 5 + n][k4 * 4];
#pragma unroll
                for (int m = 0; m < 2; m++)
#pragma unroll
                    for (int n = 0; n < 5; n++) {
                        acc[m][n] += av[m].x * wv[n].x;
                        acc[m][n] += av[m].y * wv[n].y;
                        acc[m][n] += av[m].z * wv[n].z;
                        acc[m][n] += av[m].w * wv[n].w;
                    }
            }
        }
        __syncthreads();
    }

    if (colg < 30) {
#pragma unroll
        for (int n = 0; n < 5; n++) {
            const int c = colg * 5 + n;
            const float bias = bf[c];
#pragma unroll
            for (int m = 0; m < 2; m++) {
                const int b = b0 + rowg + 8 * m;
                out[(size_t)b * N_CLASSES + c] = acc[m][n] + bias;
            }
        }
    }
}

extern "C" void kernel_launch(void* const* d_in, const int* in_sizes, int n_in,
                              void* d_out, int out_size)
{
    const float* features = (const float*)d_in[0];
    const float* Wp       = (const float*)d_in[1];
    const float* bp       = (const float*)d_in[2];
    const float* qw       = (const float*)d_in[3];
    const float* Wf       = (const float*)d_in[4];
    const float* bf       = (const float*)d_in[5];
    float* out = (float*)d_out;

    cudaFuncSetAttribute(gemm_kernel, cudaFuncAttributeMaxDynamicSharedMemorySize, 65536);

    useg_kernel<<<dim3(N_MOD, 2), 64>>>(qw);
    combine_kernel<<<dim3(N_MOD, 4), 128>>>();
    gemm_kernel<<<dim3(B_TOTAL / 64, N_MOD), 128, 65536>>>(features, Wp, bp);
    head_kernel<<<B_TOTAL / HB_M, 256>>>(Wf, bf, out);
}